// round 13
// baseline (speedup 1.0000x reference)
#include <cuda_runtime.h>
#include <cuda_bf16.h>
#include <cstdint>

#define N_DAGS 16384
#define NN     48
#define DF     62
#define NCLS   500
#define K2B    256
#define TCB    16          // dags per block in k_dag_tc

typedef unsigned long long ull;

// ---------------- scratch ----------------
__device__ float g_pre [(size_t)N_DAGS * NN * 64];   // atomP+bias OR relu'd single (pred-less)
__device__ float g_last [N_DAGS * 64];
__device__ float g_score[N_DAGS];
__device__ float g_partP[K2B * 64];
__device__ float g_partS[K2B];
__device__ float g_partM[K2B];

// ---------------- helpers ----------------
__device__ __forceinline__ float warp_sum(float v) {
    #pragma unroll
    for (int o = 16; o > 0; o >>= 1) v += __shfl_xor_sync(0xffffffffu, v, o);
    return v;
}
__device__ __forceinline__ int max4(int4 q) { return max(max(q.x, q.y), max(q.z, q.w)); }

__device__ __forceinline__ uint32_t smem_u32(const void* p) {
    return (uint32_t)__cvta_generic_to_shared(p);
}
__device__ __forceinline__ void ldm_x4(unsigned r[4], uint32_t addr) {
    asm volatile("ldmatrix.sync.aligned.m8n8.x4.shared.b16 {%0,%1,%2,%3}, [%4];"
        : "=r"(r[0]), "=r"(r[1]), "=r"(r[2]), "=r"(r[3]) : "r"(addr));
}
__device__ __forceinline__ void ldm_x2t(unsigned r[2], uint32_t addr) {
    asm volatile("ldmatrix.sync.aligned.m8n8.x2.trans.shared.b16 {%0,%1}, [%2];"
        : "=r"(r[0]), "=r"(r[1]) : "r"(addr));
}
__device__ __forceinline__ void mma16816(float d[4], const unsigned a[4], const unsigned b[2]) {
    asm volatile("mma.sync.aligned.m16n8k16.row.col.f32.bf16.bf16.f32 "
        "{%0,%1,%2,%3}, {%4,%5,%6,%7}, {%8,%9}, {%0,%1,%2,%3};"
        : "+f"(d[0]), "+f"(d[1]), "+f"(d[2]), "+f"(d[3])
        : "r"(a[0]), "r"(a[1]), "r"(a[2]), "r"(a[3]), "r"(b[0]), "r"(b[1]));
}
__device__ __forceinline__ unsigned pack_bf16x2(float lo, float hi) {
    unsigned r;
    asm("cvt.rn.bf16x2.f32 %0, %1, %2;" : "=r"(r) : "f"(hi), "f"(lo));
    return r;
}

// =================================================================
// k_pre: g_pre[node][g] = sum_f Wm[g][62+f]*atoms[node][f] + bm[g]
// Split-bf16 3-product GEMM (validated R10/R11).
// =================================================================
#define PSTRIDE 72

__global__ void __launch_bounds__(128)
k_pre(const float* __restrict__ atoms, const float* __restrict__ Wm,
      const float* __restrict__ bm) {
    __shared__ __align__(16) __nv_bfloat16 sAh[64 * PSTRIDE];
    __shared__ __align__(16) __nv_bfloat16 sAl[64 * PSTRIDE];
    __shared__ __align__(16) __nv_bfloat16 sWh[64 * PSTRIDE];
    __shared__ __align__(16) __nv_bfloat16 sWl[64 * PSTRIDE];
    __shared__ float sBm[64];

    const int tid = threadIdx.x, lane = tid & 31, warp = tid >> 5;
    const size_t row0 = (size_t)blockIdx.x * 64;

    for (int i = tid; i < 64 * 64; i += 128) {
        int f = i >> 6, g = i & 63;
        float w = (f < DF && g < DF) ? __ldg(&Wm[g * 124 + DF + f]) : 0.f;
        __nv_bfloat16 h = __float2bfloat16(w);
        sWh[f * PSTRIDE + g] = h;
        sWl[f * PSTRIDE + g] = __float2bfloat16(w - __bfloat162float(h));
    }
    if (tid < 64) sBm[tid] = (tid < DF) ? __ldg(&bm[tid]) : 0.f;

    for (int i = tid; i < 64 * 64; i += 128) {
        int r = i >> 6, c = i & 63;
        float a = (c < DF) ? __ldg(&atoms[(row0 + r) * DF + c]) : 0.f;
        __nv_bfloat16 h = __float2bfloat16(a);
        sAh[r * PSTRIDE + c] = h;
        sAl[r * PSTRIDE + c] = __float2bfloat16(a - __bfloat162float(h));
    }
    __syncthreads();

    unsigned ah[4][4], al[4][4];
    {
        uint32_t aoff = ((warp * 16 + (lane & 15)) * PSTRIDE) * 2 + (lane >> 4) * 16;
        uint32_t aH = smem_u32(sAh) + aoff, aL = smem_u32(sAl) + aoff;
        #pragma unroll
        for (int k = 0; k < 4; k++) {
            ldm_x4(ah[k], aH + k * 32);
            ldm_x4(al[k], aL + k * 32);
        }
    }

    const uint32_t bRow = (lane & 15) * (PSTRIDE * 2);
    #pragma unroll
    for (int n = 0; n < 8; n++) {
        float d[4] = {0.f, 0.f, 0.f, 0.f};
        #pragma unroll
        for (int k = 0; k < 4; k++) {
            unsigned bh[2], blo[2];
            uint32_t boff = (uint32_t)(k * 16 * PSTRIDE * 2) + bRow + n * 16;
            ldm_x2t(bh,  smem_u32(sWh) + boff);
            ldm_x2t(blo, smem_u32(sWl) + boff);
            mma16816(d, ah[k], bh);
            mma16816(d, al[k], bh);
            mma16816(d, ah[k], blo);
        }
        int r = lane >> 2;
        int c = n * 8 + 2 * (lane & 3);
        float b0 = sBm[c], b1 = sBm[c + 1];
        size_t ro = (row0 + warp * 16 + r) * 64 + c;
        *(float2*)&g_pre[ro]           = make_float2(d[0] + b0, d[1] + b1);
        *(float2*)&g_pre[ro + 8 * 64]  = make_float2(d[2] + b0, d[3] + b1);
    }
}

// =================================================================
// k_single: overwrite g_pre slots of pred-less nodes with the final
// relu'd single value. One warp per DAG; ~1.08 nodes per DAG.
// =================================================================
__global__ void __launch_bounds__(128)
k_single(const float* __restrict__ atoms, const int* __restrict__ preds,
         const float* __restrict__ Ws, const float* __restrict__ bs) {
    const int tid = threadIdx.x, lane = tid & 31, warp = tid >> 5;
    const int d = blockIdx.x * 4 + warp;
    if (d >= N_DAGS) return;
    const int r0 = 2 * lane, r1 = r0 + 1;
    const bool a0 = (r0 < DF), a1 = (r1 < DF);

    const int4* P = (const int4*)preds + (size_t)d * NN;
    int4 q = __ldg(P + lane);
    unsigned bl = __ballot_sync(0xffffffffu, max4(q) >= 0);
    bool h = true;
    if (lane < 16) { int4 q2 = __ldg(P + 32 + lane); h = max4(q2) >= 0; }
    unsigned bh = __ballot_sync(0xffffffffu, h);

    ull miss = (ull)(~bl) | ((ull)((~bh) & 0xffffu) << 32);
    while (miss) {
        int t = __ffsll(miss) - 1;
        miss &= miss - 1;
        const float* ar = atoms + ((size_t)d * NN + t) * DF;
        float acc0 = a0 ? __ldg(&bs[r0]) : 0.f;
        float acc1 = a1 ? __ldg(&bs[r1]) : 0.f;
        #pragma unroll 31
        for (int f = 0; f < DF; f++) {
            float xv = __ldg(ar + f);
            if (a0) acc0 = fmaf(__ldg(&Ws[r0 * DF + f]), xv, acc0);
            if (a1) acc1 = fmaf(__ldg(&Ws[r1 * DF + f]), xv, acc1);
        }
        float v0 = fmaxf(acc0, 0.f), v1 = fmaxf(acc1, 0.f);
        *(float2*)&g_pre[((size_t)d * NN + t) * 64 + r0] =
            make_float2(a0 ? v0 : 0.f, a1 ? v1 : 0.f);
    }
}

// =================================================================
// k_dag_tc: DAG-batched recurrence on tensor cores.
// 16 DAGs per block (256 thr, 1 block/SM). Per step:
//   phase A: softmax+aggregate -> X (split bf16)    [8 warps x 2 dags]
//   phase B: [16x64]x[64x64] mma (3-product split) + epilogue
// Pred-less nodes: X row = 0 => out = relu(0 + staged single) = single.
// =================================================================
// smem byte offsets
#define O_OUT  0                   // 16*48*64 f32 = 196608
#define O_XH   196608              // 16*72 bf16 = 2304
#define O_XL   198912              // 2304
#define O_SCB  201216              // 16*48*8 f32 = 24576
#define O_PRD  225792              // 16*48 char4 = 3072
#define TC_SMEM 228864

__global__ void __launch_bounds__(256, 1)
k_dag_tc(const int* __restrict__ preds, const float* __restrict__ Wm,
         const float* __restrict__ attw, const float* __restrict__ dagw) {
    extern __shared__ char SMC[];
    float* OUT = (float*)(SMC + O_OUT);
    float* SCB = (float*)(SMC + O_SCB);
    char4* PRD = (char4*)(SMC + O_PRD);

    const int tid = threadIdx.x, lane = tid & 31, w = tid >> 5;

    // ---- W_x fragments (stage in OUT-region alias, extract, release) ----
    unsigned bhf[4][2], blf[4][2];
    {
        __nv_bfloat16* sWh = (__nv_bfloat16*)SMC;            // 9216 B
        __nv_bfloat16* sWl = (__nv_bfloat16*)(SMC + 9216);   // 9216 B
        for (int i = tid; i < 64 * 64; i += 256) {
            int k = i >> 6, n = i & 63;
            float wv = (k < DF && n < DF) ? __ldg(&Wm[n * 124 + k]) : 0.f;
            __nv_bfloat16 hh = __float2bfloat16(wv);
            sWh[k * 72 + n] = hh;
            sWl[k * 72 + n] = __float2bfloat16(wv - __bfloat162float(hh));
        }
        __syncthreads();
        #pragma unroll
        for (int k = 0; k < 4; k++) {
            uint32_t boff = (uint32_t)(k * 16 * 144) + (lane & 15) * 144 + w * 16;
            ldm_x2t(bhf[k], smem_u32(sWh) + boff);
            ldm_x2t(blf[k], smem_u32(sWl) + boff);
        }
        __syncthreads();
    }

    // per-thread constants
    const int c0 = w * 8 + 2 * (lane & 3);           // epilogue cols (c0, c0+1)
    const float awc0 = (c0     < DF) ? __ldg(&attw[c0])     : 0.f;
    const float awc1 = (c0 + 1 < DF) ? __ldg(&attw[c0 + 1]) : 0.f;
    const int dagA = lane >> 2;                      // epilogue rows dagA, dagA+8
    const int ga = 2 * lane;                         // phase-A cols (ga, ga+1)

    for (int batch = blockIdx.x; batch < N_DAGS / TCB; batch += gridDim.x) {
        const size_t dbase = (size_t)batch * TCB;

        // ---- stage g_pre tile + preds ----
        {
            const float4* src = (const float4*)(g_pre + dbase * (NN * 64));
            float4* dst = (float4*)OUT;
            #pragma unroll 8
            for (int i = tid; i < TCB * NN * 16; i += 256)
                dst[i] = __ldg(src + i);
            for (int i = tid; i < TCB * NN; i += 256) {
                int4 q = __ldg((const int4*)preds + dbase * NN + i);
                PRD[i] = make_char4((char)q.x, (char)q.y, (char)q.z, (char)q.w);
            }
        }
        __syncthreads();

        // ================= step loop =================
        for (int t = 0; t < NN; t++) {
            // ---- phase A: softmax + aggregate -> X (warp w: dags w, w+8) ----
            #pragma unroll
            for (int e = 0; e < 2; e++) {
                const int dd = w + e * 8;
                char4 pc = PRD[dd * NN + t];
                unsigned* xhw = (unsigned*)(SMC + O_XH + dd * 144 + lane * 4);
                unsigned* xlw = (unsigned*)(SMC + O_XL + dd * 144 + lane * 4);
                const bool v0 = pc.x >= 0, v1 = pc.y >= 0, v2 = pc.z >= 0, v3 = pc.w >= 0;
                if (!(v0 | v1 | v2 | v3)) {           // pred-less: zero X row
                    *xhw = 0u; *xlw = 0u;
                    continue;
                }
                const int q0 = max((int)pc.x, 0), q1 = max((int)pc.y, 0);
                const int q2 = max((int)pc.z, 0), q3 = max((int)pc.w, 0);
                const float* SC = SCB + dd * (NN * 8);
                float4 ca = *(float4*)&SC[q0 * 8], cb = *(float4*)&SC[q0 * 8 + 4];
                float s0 = v0 ? (ca.x + ca.y + ca.z + ca.w + cb.x + cb.y + cb.z + cb.w) : -1e30f;
                ca = *(float4*)&SC[q1 * 8]; cb = *(float4*)&SC[q1 * 8 + 4];
                float s1 = v1 ? (ca.x + ca.y + ca.z + ca.w + cb.x + cb.y + cb.z + cb.w) : -1e30f;
                ca = *(float4*)&SC[q2 * 8]; cb = *(float4*)&SC[q2 * 8 + 4];
                float s2 = v2 ? (ca.x + ca.y + ca.z + ca.w + cb.x + cb.y + cb.z + cb.w) : -1e30f;
                ca = *(float4*)&SC[q3 * 8]; cb = *(float4*)&SC[q3 * 8 + 4];
                float s3 = v3 ? (ca.x + ca.y + ca.z + ca.w + cb.x + cb.y + cb.z + cb.w) : -1e30f;
                float m = fmaxf(fmaxf(s0, s1), fmaxf(s2, s3));
                float e0 = v0 ? __expf(s0 - m) : 0.f;
                float e1 = v1 ? __expf(s1 - m) : 0.f;
                float e2 = v2 ? __expf(s2 - m) : 0.f;
                float e3 = v3 ? __expf(s3 - m) : 0.f;
                float inv = 1.f / (e0 + e1 + e2 + e3);
                const float* OD = OUT + dd * (NN * 64);
                float2 u0 = *(float2*)&OD[q0 * 64 + ga];
                float2 u1 = *(float2*)&OD[q1 * 64 + ga];
                float2 u2 = *(float2*)&OD[q2 * 64 + ga];
                float2 u3 = *(float2*)&OD[q3 * 64 + ga];
                float x0 = (e0 * u0.x + e1 * u1.x + e2 * u2.x + e3 * u3.x) * inv;
                float x1 = (e0 * u0.y + e1 * u1.y + e2 * u2.y + e3 * u3.y) * inv;
                // split bf16
                __nv_bfloat16 h0 = __float2bfloat16(x0), h1 = __float2bfloat16(x1);
                float l0 = x0 - __bfloat162float(h0), l1 = x1 - __bfloat162float(h1);
                *xhw = ((unsigned)__bfloat16_as_ushort(h1) << 16) | __bfloat16_as_ushort(h0);
                *xlw = pack_bf16x2(l0, l1);
            }
            __syncthreads();   // X ready

            // ---- phase B: GEMM + epilogue ----
            {
                unsigned ah[4][4], al[4][4];
                uint32_t aoff = (lane & 15) * 144 + (lane >> 4) * 16;
                uint32_t aH = smem_u32(SMC + O_XH) + aoff;
                uint32_t aL = smem_u32(SMC + O_XL) + aoff;
                #pragma unroll
                for (int k = 0; k < 4; k++) {
                    ldm_x4(ah[k], aH + k * 32);
                    ldm_x4(al[k], aL + k * 32);
                }
                float d[4] = {0.f, 0.f, 0.f, 0.f};
                #pragma unroll
                for (int k = 0; k < 4; k++) {
                    mma16816(d, ah[k], bhf[k]);
                    mma16816(d, al[k], bhf[k]);
                    mma16816(d, ah[k], blf[k]);
                }
                float* oA = OUT + dagA * (NN * 64) + t * 64 + c0;
                float* oB = oA + 8 * (NN * 64);
                float2 apA = *(float2*)oA;
                float2 apB = *(float2*)oB;
                float oA0 = fmaxf(d[0] + apA.x, 0.f), oA1 = fmaxf(d[1] + apA.y, 0.f);
                float oB0 = fmaxf(d[2] + apB.x, 0.f), oB1 = fmaxf(d[3] + apB.y, 0.f);
                *(float2*)oA = make_float2(oA0, oA1);
                *(float2*)oB = make_float2(oB0, oB1);
                float pA = oA0 * awc0 + oA1 * awc1;
                float pB = oB0 * awc0 + oB1 * awc1;
                pA += __shfl_xor_sync(0xffffffffu, pA, 1);
                pA += __shfl_xor_sync(0xffffffffu, pA, 2);
                pB += __shfl_xor_sync(0xffffffffu, pB, 1);
                pB += __shfl_xor_sync(0xffffffffu, pB, 2);
                if ((lane & 3) == 0) {
                    SCB[dagA * (NN * 8) + t * 8 + w]       = pA;
                    SCB[(dagA + 8) * (NN * 8) + t * 8 + w] = pB;
                }
            }
            __syncthreads();   // OUT[t], SCB[t] ready
        }

        // ---- finalize 16 dags ----
        for (int i = tid; i < TCB * 64; i += 256) {
            int dd = i >> 6, c = i & 63;
            g_last[(dbase + dd) * 64 + c] = OUT[dd * (NN * 64) + 47 * 64 + c];
        }
        {
            const float dg0 = (ga     < DF) ? __ldg(&dagw[ga])     : 0.f;
            const float dg1 = (ga + 1 < DF) ? __ldg(&dagw[ga + 1]) : 0.f;
            #pragma unroll
            for (int e = 0; e < 2; e++) {
                int dd = w + e * 8;
                float2 l = *(float2*)&OUT[dd * (NN * 64) + 47 * 64 + ga];
                float v = l.x * dg0 + l.y * dg1;
                v = warp_sum(v);
                if (lane == 0) g_score[dbase + dd] = v;
            }
        }
        __syncthreads();
    }
}

// =================================================================
// k_pool_partial: deterministic partial softmax pooling over 64 DAGs
// =================================================================
__global__ void k_pool_partial() {
    __shared__ float sm_e[64];
    __shared__ float sm_red[4];
    int tid = threadIdx.x;        // 128
    int b = blockIdx.x;
    int d0 = b * 64;

    float s = (tid < 64) ? g_score[d0 + tid] : -1e30f;
    float v = s;
    #pragma unroll
    for (int o = 16; o > 0; o >>= 1) v = fmaxf(v, __shfl_xor_sync(0xffffffffu, v, o));
    if ((tid & 31) == 0 && tid < 64) sm_red[tid >> 5] = v;
    __syncthreads();
    float m = fmaxf(sm_red[0], sm_red[1]);

    float e = (tid < 64) ? __expf(s - m) : 0.f;
    if (tid < 64) sm_e[tid] = e;
    float se = warp_sum(e);
    if ((tid & 31) == 0 && tid < 64) sm_red[2 + (tid >> 5)] = se;
    __syncthreads();
    if (tid == 0) { g_partS[b] = sm_red[2] + sm_red[3]; g_partM[b] = m; }
    if (tid < DF) {
        float acc = 0.f;
        #pragma unroll 8
        for (int dd = 0; dd < 64; dd++)
            acc = fmaf(sm_e[dd], g_last[(size_t)(d0 + dd) * 64 + tid], acc);
        g_partP[b * 64 + tid] = acc;
    }
}

// =================================================================
// k_final: combine partials -> pooled -> sigmoid(W_final @ pooled + b)
// =================================================================
__global__ void k_final(const float* __restrict__ Wf, const float* __restrict__ bf,
                        float* __restrict__ out) {
    __shared__ float sw[K2B];
    __shared__ float smMax[16];
    __shared__ float smSum[16];
    __shared__ float smScalar[2];
    __shared__ float part8[8][64];
    __shared__ float pooled[64];
    int tid = threadIdx.x;        // 512
    int lane = tid & 31, warp = tid >> 5;

    float m = (tid < K2B) ? g_partM[tid] : -1e30f;
    float v = m;
    #pragma unroll
    for (int o = 16; o > 0; o >>= 1) v = fmaxf(v, __shfl_xor_sync(0xffffffffu, v, o));
    if (lane == 0) smMax[warp] = v;
    __syncthreads();
    if (tid == 0) {
        float M = smMax[0];
        #pragma unroll
        for (int w = 1; w < 16; w++) M = fmaxf(M, smMax[w]);
        smScalar[0] = M;
    }
    __syncthreads();
    float M = smScalar[0];

    float wb = (tid < K2B) ? __expf(m - M) : 0.f;
    if (tid < K2B) sw[tid] = wb;
    float ss = (tid < K2B) ? g_partS[tid] * wb : 0.f;
    ss = warp_sum(ss);
    if (lane == 0) smSum[warp] = ss;
    __syncthreads();
    if (tid == 0) {
        float S = 0.f;
        #pragma unroll
        for (int w = 0; w < 16; w++) S += smSum[w];
        smScalar[1] = 1.f / S;
    }
    __syncthreads();
    float invS = smScalar[1];

    {
        int grp = tid >> 6, gg = tid & 63;
        float acc = 0.f;
        int b0 = grp * 32;
        #pragma unroll 8
        for (int b2 = b0; b2 < b0 + 32; b2++)
            acc = fmaf(sw[b2], g_partP[b2 * 64 + gg], acc);
        part8[grp][gg] = acc;
    }
    __syncthreads();
    if (tid < DF) {
        float acc = 0.f;
        #pragma unroll
        for (int c = 0; c < 8; c++) acc += part8[c][tid];
        pooled[tid] = acc * invS;
    }
    if (tid >= DF && tid < 64) pooled[tid] = 0.f;
    __syncthreads();

    for (int o = tid; o < NCLS; o += 512) {
        float acc = bf[o];
        #pragma unroll
        for (int gg = 0; gg < DF; gg++) acc = fmaf(Wf[o * DF + gg], pooled[gg], acc);
        out[o] = 1.f / (1.f + __expf(-acc));
    }
}

// =================================================================
extern "C" void kernel_launch(void* const* d_in, const int* in_sizes, int n_in,
                              void* d_out, int out_size) {
    const float* atoms = (const float*)d_in[0];
    const int*   preds = (const int*)  d_in[1];
    const float* Ws    = (const float*)d_in[2];
    const float* bs    = (const float*)d_in[3];
    const float* Wm    = (const float*)d_in[4];
    const float* bm    = (const float*)d_in[5];
    const float* attw  = (const float*)d_in[6];
    const float* dagw  = (const float*)d_in[7];
    const float* Wf    = (const float*)d_in[8];
    const float* bf    = (const float*)d_in[9];
    float* out = (float*)d_out;

    cudaFuncSetAttribute(k_dag_tc, cudaFuncAttributeMaxDynamicSharedMemorySize, TC_SMEM);

    k_pre<<<(N_DAGS * NN) / 64, 128>>>(atoms, Wm, bm);
    k_single<<<N_DAGS / 4, 128>>>(atoms, preds, Ws, bs);
    k_dag_tc<<<148, 256, TC_SMEM>>>(preds, Wm, attw, dagw);
    k_pool_partial<<<K2B, 128>>>();
    k_final<<<1, 512>>>(Wf, bf, out);
}

// round 14
// speedup vs baseline: 1.4978x; 1.4978x over previous
#include <cuda_runtime.h>
#include <cuda_bf16.h>
#include <cstdint>

#define N_DAGS 16384
#define NN     48
#define DF     62
#define NCLS   500
#define K2B    256

typedef unsigned long long ull;

// ---------------- scratch ----------------
__device__ float g_pre [(size_t)N_DAGS * NN * 64];   // atomP + b_merge, 64-padded
__device__ float g_last [N_DAGS * 64];
__device__ float g_score[N_DAGS];
__device__ float g_partP[K2B * 64];
__device__ float g_partS[K2B];
__device__ float g_partM[K2B];
__device__ unsigned g_ctr;

// ---------------- packed f32x2 helpers ----------------
__device__ __forceinline__ ull ffma2(ull a, ull b, ull c) {
    ull d;
    asm("fma.rn.f32x2 %0, %1, %2, %3;" : "=l"(d) : "l"(a), "l"(b), "l"(c));
    return d;
}
__device__ __forceinline__ ull pack2(float a, float b) {
    return (ull)__float_as_uint(a) | ((ull)__float_as_uint(b) << 32);
}
__device__ __forceinline__ float lo2(ull v) { return __uint_as_float((unsigned)v); }
__device__ __forceinline__ float hi2(ull v) { return __uint_as_float((unsigned)(v >> 32)); }

__device__ __forceinline__ float warp_sum(float v) {
    #pragma unroll
    for (int o = 16; o > 0; o >>= 1) v += __shfl_xor_sync(0xffffffffu, v, o);
    return v;
}
__device__ __forceinline__ float red8(float v) {
    v += __shfl_xor_sync(0xffffffffu, v, 4);
    v += __shfl_xor_sync(0xffffffffu, v, 2);
    v += __shfl_xor_sync(0xffffffffu, v, 1);
    return v;
}
__device__ __forceinline__ int max4(int4 q) { return max(max(q.x, q.y), max(q.z, q.w)); }
__device__ __forceinline__ bool mbit(unsigned bl, unsigned bh, int t) {
    return (t < 32) ? ((bl >> t) & 1u) : ((bh >> (t - 32)) & 1u);
}

// ---------------- mma helpers (bf16 m16n8k16) ----------------
__device__ __forceinline__ uint32_t smem_u32(const void* p) {
    return (uint32_t)__cvta_generic_to_shared(p);
}
__device__ __forceinline__ void ldm_x4(unsigned r[4], uint32_t addr) {
    asm volatile("ldmatrix.sync.aligned.m8n8.x4.shared.b16 {%0,%1,%2,%3}, [%4];"
        : "=r"(r[0]), "=r"(r[1]), "=r"(r[2]), "=r"(r[3]) : "r"(addr));
}
__device__ __forceinline__ void ldm_x2t(unsigned r[2], uint32_t addr) {
    asm volatile("ldmatrix.sync.aligned.m8n8.x2.trans.shared.b16 {%0,%1}, [%2];"
        : "=r"(r[0]), "=r"(r[1]) : "r"(addr));
}
__device__ __forceinline__ void mma16816(float d[4], const unsigned a[4], const unsigned b[2]) {
    asm volatile("mma.sync.aligned.m16n8k16.row.col.f32.bf16.bf16.f32 "
        "{%0,%1,%2,%3}, {%4,%5,%6,%7}, {%8,%9}, {%0,%1,%2,%3};"
        : "+f"(d[0]), "+f"(d[1]), "+f"(d[2]), "+f"(d[3])
        : "r"(a[0]), "r"(a[1]), "r"(a[2]), "r"(a[3]), "r"(b[0]), "r"(b[1]));
}

// =================================================================
// k_zero: reset the work-stealing counter (runs before k_dag)
// =================================================================
__global__ void k_zero() { g_ctr = 0u; }

// =================================================================
// k_pre: g_pre[node][g] = sum_f Wm[g][62+f]*atoms[node][f] + bm[g]
// Split-bf16 3-product GEMM. 4 row-tiles (256 rows) per block:
// W staged/converted ONCE per block.
// =================================================================
#define PSTRIDE 72

__global__ void __launch_bounds__(128)
k_pre(const float* __restrict__ atoms, const float* __restrict__ Wm,
      const float* __restrict__ bm) {
    __shared__ __align__(16) __nv_bfloat16 sAh[64 * PSTRIDE];
    __shared__ __align__(16) __nv_bfloat16 sAl[64 * PSTRIDE];
    __shared__ __align__(16) __nv_bfloat16 sWh[64 * PSTRIDE];
    __shared__ __align__(16) __nv_bfloat16 sWl[64 * PSTRIDE];
    __shared__ float sBm[64];

    const int tid = threadIdx.x, lane = tid & 31, warp = tid >> 5;

    // ---- W (k-major: [f][g]) + bias: once per block ----
    for (int i = tid; i < 64 * 64; i += 128) {
        int f = i >> 6, g = i & 63;
        float w = (f < DF && g < DF) ? __ldg(&Wm[g * 124 + DF + f]) : 0.f;
        __nv_bfloat16 h = __float2bfloat16(w);
        sWh[f * PSTRIDE + g] = h;
        sWl[f * PSTRIDE + g] = __float2bfloat16(w - __bfloat162float(h));
    }
    if (tid < 64) sBm[tid] = (tid < DF) ? __ldg(&bm[tid]) : 0.f;

    #pragma unroll 1
    for (int tile = 0; tile < 4; tile++) {
        const size_t row0 = (size_t)blockIdx.x * 256 + (size_t)tile * 64;
        __syncthreads();   // prior tile's reads of sA done (also orders W stage)

        for (int i = tid; i < 64 * 64; i += 128) {
            int r = i >> 6, c = i & 63;
            float a = (c < DF) ? __ldg(&atoms[(row0 + r) * DF + c]) : 0.f;
            __nv_bfloat16 h = __float2bfloat16(a);
            sAh[r * PSTRIDE + c] = h;
            sAl[r * PSTRIDE + c] = __float2bfloat16(a - __bfloat162float(h));
        }
        __syncthreads();

        unsigned ah[4][4], al[4][4];
        {
            uint32_t aoff = ((warp * 16 + (lane & 15)) * PSTRIDE) * 2 + (lane >> 4) * 16;
            uint32_t aH = smem_u32(sAh) + aoff, aL = smem_u32(sAl) + aoff;
            #pragma unroll
            for (int k = 0; k < 4; k++) {
                ldm_x4(ah[k], aH + k * 32);
                ldm_x4(al[k], aL + k * 32);
            }
        }

        const uint32_t bRow = (lane & 15) * (PSTRIDE * 2);
        #pragma unroll
        for (int n = 0; n < 8; n++) {
            float d[4] = {0.f, 0.f, 0.f, 0.f};
            #pragma unroll
            for (int k = 0; k < 4; k++) {
                unsigned bh[2], blo[2];
                uint32_t boff = (uint32_t)(k * 16 * PSTRIDE * 2) + bRow + n * 16;
                ldm_x2t(bh,  smem_u32(sWh) + boff);
                ldm_x2t(blo, smem_u32(sWl) + boff);
                mma16816(d, ah[k], bh);
                mma16816(d, al[k], bh);
                mma16816(d, ah[k], blo);
            }
            int r = lane >> 2;
            int c = n * 8 + 2 * (lane & 3);
            float b0 = sBm[c], b1 = sBm[c + 1];
            size_t ro = (row0 + warp * 16 + r) * 64 + c;
            *(float2*)&g_pre[ro]           = make_float2(d[0] + b0, d[1] + b1);
            *(float2*)&g_pre[ro + 8 * 64]  = make_float2(d[2] + b0, d[3] + b1);
        }
    }
}

// per-warp smem region: 3520 floats (14080 B)
#define RWF    3520
#define W_OUT  0
#define W_XS   3072
#define W_SCB  3136
#define W_PRD  3328
#define DSM_BYTES (4 * RWF * 4)   // 56320

// =================================================================
// k_dag: recurrent loop. ONE WARP = ONE DAG, dynamic work-stealing.
// Thread owns rows (2*lane, 2*lane+1); x-half merge weights in regs,
// loaded ONCE per kernel.
// =================================================================
__global__ void __launch_bounds__(128, 3)
k_dag(const float* __restrict__ atoms, const int* __restrict__ preds,
      const float* __restrict__ Wm,   const float* __restrict__ Ws,
      const float* __restrict__ bs,   const float* __restrict__ attw,
      const float* __restrict__ dagw) {
    extern __shared__ float DSM[];
    const int tid = threadIdx.x, lane = tid & 31, warp = tid >> 5;
    float* R   = DSM + warp * RWF;
    float* OUT = R + W_OUT;
    float* XS  = R + W_XS;
    float* SCB = R + W_SCB;
    int*   PRD = (int*)(R + W_PRD);

    const int r0 = 2 * lane, r1 = 2 * lane + 1;
    const bool a0 = (r0 < DF), a1 = (r1 < DF);
    const float aw0 = a0 ? attw[r0] : 0.f, aw1 = a1 ? attw[r1] : 0.f;

    // x-half merge weights: loaded once
    ull W[64];
    #pragma unroll
    for (int j = 0; j < 32; j++) {
        W[j]      = (a0 && j < 31) ? pack2(__ldg(&Wm[r0*124 + 2*j]), __ldg(&Wm[r0*124 + 2*j + 1])) : 0ull;
        W[32 + j] = (a1 && j < 31) ? pack2(__ldg(&Wm[r1*124 + 2*j]), __ldg(&Wm[r1*124 + 2*j + 1])) : 0ull;
    }

    #pragma unroll 1
    for (;;) {
        // ---- dynamic ticket ----
        int d;
        if (lane == 0) d = (int)atomicAdd(&g_ctr, 1u);
        d = __shfl_sync(0xffffffffu, d, 0);
        if (d >= N_DAGS) break;

        // ---- preds + masks ----
        unsigned bl, bh;
        {
            const int4* P = (const int4*)(preds + (size_t)d * NN * 4);
            int4 q = __ldg(P + lane); ((int4*)PRD)[lane] = q;
            bl = __ballot_sync(0xffffffffu, max4(q) >= 0);
            bool h = true;
            if (lane < 16) { int4 q2 = __ldg(P + 32 + lane); ((int4*)PRD)[32 + lane] = q2; h = max4(q2) >= 0; }
            bh = __ballot_sync(0xffffffffu, h);
        }

        // ---- stage g_pre tile (atomP + bias, 64-padded with zeros) ----
        {
            const float4* src = (const float4*)(g_pre + (size_t)d * (NN * 64));
            #pragma unroll
            for (int k = 0; k < 24; k++)
                ((float4*)OUT)[lane + 32 * k] = __ldg(src + lane + 32 * k);
        }
        __syncwarp();

        // ---- pred-less nodes (t=0 always + rare): single path from gmem ----
        {
            ull miss = (ull)(~bl) | ((ull)((~bh) & 0xffffu) << 32);
            while (miss) {
                int t = __ffsll(miss) - 1;
                miss &= miss - 1;
                const float* ar = atoms + ((size_t)d * NN + t) * DF;
                float acc0 = a0 ? __ldg(&bs[r0]) : 0.f;
                float acc1 = a1 ? __ldg(&bs[r1]) : 0.f;
                #pragma unroll 31
                for (int f = 0; f < DF; f++) {
                    float xv = __ldg(ar + f);
                    if (a0) acc0 = fmaf(__ldg(&Ws[r0 * DF + f]), xv, acc0);
                    if (a1) acc1 = fmaf(__ldg(&Ws[r1 * DF + f]), xv, acc1);
                }
                float v0 = fmaxf(acc0, 0.f), v1 = fmaxf(acc1, 0.f);
                *(float2*)&OUT[t * 64 + r0] = make_float2(a0 ? v0 : 0.f, a1 ? v1 : 0.f);
                float c = v0 * aw0 + v1 * aw1;
                c = warp_sum(c);
                if (lane < 4) SCB[t * 4 + lane] = (lane == 0) ? c : 0.f;
            }
        }
        __syncwarp();

        // ================= recurrent step loop =================
        for (int t = 1; t < NN; t++) {
            if (!mbit(bl, bh, t)) continue;   // warp-uniform; pred-less already done

            // ---- phase A: softmax + aggregate -> XS ----
            int4 p = ((const int4*)PRD)[t];
            int q0 = max(p.x,0), q1 = max(p.y,0), q2 = max(p.z,0), q3 = max(p.w,0);
            float4 c0 = *(float4*)&SCB[q0*4];
            float4 c1 = *(float4*)&SCB[q1*4];
            float4 c2 = *(float4*)&SCB[q2*4];
            float4 c3 = *(float4*)&SCB[q3*4];
            float s0 = (p.x >= 0) ? (c0.x+c0.y+c0.z+c0.w) : -1e30f;
            float s1 = (p.y >= 0) ? (c1.x+c1.y+c1.z+c1.w) : -1e30f;
            float s2 = (p.z >= 0) ? (c2.x+c2.y+c2.z+c2.w) : -1e30f;
            float s3 = (p.w >= 0) ? (c3.x+c3.y+c3.z+c3.w) : -1e30f;
            float m = fmaxf(fmaxf(s0, s1), fmaxf(s2, s3));
            float e0 = (p.x >= 0) ? __expf(s0 - m) : 0.f;
            float e1 = (p.y >= 0) ? __expf(s1 - m) : 0.f;
            float e2 = (p.z >= 0) ? __expf(s2 - m) : 0.f;
            float e3 = (p.w >= 0) ? __expf(s3 - m) : 0.f;
            float inv = 1.f / (e0 + e1 + e2 + e3);
            float2 u0 = *(float2*)&OUT[q0*64 + r0];
            float2 u1 = *(float2*)&OUT[q1*64 + r0];
            float2 u2 = *(float2*)&OUT[q2*64 + r0];
            float2 u3 = *(float2*)&OUT[q3*64 + r0];
            float x0 = (e0*u0.x + e1*u1.x + e2*u2.x + e3*u3.x) * inv;
            float x1 = (e0*u0.y + e1*u1.y + e2*u2.y + e3*u3.y) * inv;
            *(float2*)&XS[r0] = make_float2(x0, x1);   // lane31 writes zeros
            __syncwarp();

            // ---- phase B: matvec + store + score partials ----
            float2 ap = *(float2*)&OUT[t*64 + r0];
            const ulonglong2* xp = (const ulonglong2*)XS;
            ull A0=0,A1=0,A2=0,A3=0,B0=0,B1=0,B2=0,B3=0;
            #pragma unroll
            for (int i = 0; i < 8; i++) {
                ulonglong2 u = xp[2*i], w = xp[2*i + 1];
                A0 = ffma2(W[4*i],      u.x, A0); A1 = ffma2(W[4*i+1],    u.y, A1);
                A2 = ffma2(W[4*i+2],    w.x, A2); A3 = ffma2(W[4*i+3],    w.y, A3);
                B0 = ffma2(W[32+4*i],   u.x, B0); B1 = ffma2(W[32+4*i+1], u.y, B1);
                B2 = ffma2(W[32+4*i+2], w.x, B2); B3 = ffma2(W[32+4*i+3], w.y, B3);
            }
            float sA = (lo2(A0)+hi2(A0)) + (lo2(A1)+hi2(A1)) + (lo2(A2)+hi2(A2)) + (lo2(A3)+hi2(A3));
            float sB = (lo2(B0)+hi2(B0)) + (lo2(B1)+hi2(B1)) + (lo2(B2)+hi2(B2)) + (lo2(B3)+hi2(B3));
            float v0 = fmaxf(sA + ap.x, 0.f), v1 = fmaxf(sB + ap.y, 0.f);
            *(float2*)&OUT[t*64 + r0] = make_float2(a0 ? v0 : 0.f, a1 ? v1 : 0.f);
            float c = v0 * aw0 + v1 * aw1;
            c = red8(c);
            if ((lane & 7) == 0) SCB[t*4 + (lane >> 3)] = c;
            __syncwarp();
        }

        // ---- finalize DAG ----
        {
            float2 last = *(float2*)&OUT[47*64 + r0];
            *(float2*)&g_last[(size_t)d*64 + r0] = last;
            const float dg0 = a0 ? __ldg(&dagw[r0]) : 0.f;
            const float dg1 = a1 ? __ldg(&dagw[r1]) : 0.f;
            float v = last.x * dg0 + last.y * dg1;
            v = warp_sum(v);
            if (lane == 0) g_score[d] = v;
        }
        __syncwarp();
    }
}

// =================================================================
// k_pool_partial: deterministic partial softmax pooling over 64 DAGs
// =================================================================
__global__ void k_pool_partial() {
    __shared__ float sm_e[64];
    __shared__ float sm_red[4];
    int tid = threadIdx.x;        // 128
    int b = blockIdx.x;
    int d0 = b * 64;

    float s = (tid < 64) ? g_score[d0 + tid] : -1e30f;
    float v = s;
    #pragma unroll
    for (int o = 16; o > 0; o >>= 1) v = fmaxf(v, __shfl_xor_sync(0xffffffffu, v, o));
    if ((tid & 31) == 0 && tid < 64) sm_red[tid >> 5] = v;
    __syncthreads();
    float m = fmaxf(sm_red[0], sm_red[1]);

    float e = (tid < 64) ? __expf(s - m) : 0.f;
    if (tid < 64) sm_e[tid] = e;
    float se = warp_sum(e);
    if ((tid & 31) == 0 && tid < 64) sm_red[2 + (tid >> 5)] = se;
    __syncthreads();
    if (tid == 0) { g_partS[b] = sm_red[2] + sm_red[3]; g_partM[b] = m; }
    if (tid < DF) {
        float acc = 0.f;
        #pragma unroll 8
        for (int dd = 0; dd < 64; dd++)
            acc = fmaf(sm_e[dd], g_last[(size_t)(d0 + dd) * 64 + tid], acc);
        g_partP[b * 64 + tid] = acc;
    }
}

// =================================================================
// k_final: combine partials -> pooled -> sigmoid(W_final @ pooled + b)
// =================================================================
__global__ void k_final(const float* __restrict__ Wf, const float* __restrict__ bf,
                        float* __restrict__ out) {
    __shared__ float sw[K2B];
    __shared__ float smMax[16];
    __shared__ float smSum[16];
    __shared__ float smScalar[2];
    __shared__ float part8[8][64];
    __shared__ float pooled[64];
    int tid = threadIdx.x;        // 512
    int lane = tid & 31, warp = tid >> 5;

    float m = (tid < K2B) ? g_partM[tid] : -1e30f;
    float v = m;
    #pragma unroll
    for (int o = 16; o > 0; o >>= 1) v = fmaxf(v, __shfl_xor_sync(0xffffffffu, v, o));
    if (lane == 0) smMax[warp] = v;
    __syncthreads();
    if (tid == 0) {
        float M = smMax[0];
        #pragma unroll
        for (int w = 1; w < 16; w++) M = fmaxf(M, smMax[w]);
        smScalar[0] = M;
    }
    __syncthreads();
    float M = smScalar[0];

    float wb = (tid < K2B) ? __expf(m - M) : 0.f;
    if (tid < K2B) sw[tid] = wb;
    float ss = (tid < K2B) ? g_partS[tid] * wb : 0.f;
    ss = warp_sum(ss);
    if (lane == 0) smSum[warp] = ss;
    __syncthreads();
    if (tid == 0) {
        float S = 0.f;
        #pragma unroll
        for (int w = 0; w < 16; w++) S += smSum[w];
        smScalar[1] = 1.f / S;
    }
    __syncthreads();
    float invS = smScalar[1];

    {
        int grp = tid >> 6, gg = tid & 63;
        float acc = 0.f;
        int b0 = grp * 32;
        #pragma unroll 8
        for (int b2 = b0; b2 < b0 + 32; b2++)
            acc = fmaf(sw[b2], g_partP[b2 * 64 + gg], acc);
        part8[grp][gg] = acc;
    }
    __syncthreads();
    if (tid < DF) {
        float acc = 0.f;
        #pragma unroll
        for (int c = 0; c < 8; c++) acc += part8[c][tid];
        pooled[tid] = acc * invS;
    }
    if (tid >= DF && tid < 64) pooled[tid] = 0.f;
    __syncthreads();

    for (int o = tid; o < NCLS; o += 512) {
        float acc = bf[o];
        #pragma unroll
        for (int gg = 0; gg < DF; gg++) acc = fmaf(Wf[o * DF + gg], pooled[gg], acc);
        out[o] = 1.f / (1.f + __expf(-acc));
    }
}

// =================================================================
extern "C" void kernel_launch(void* const* d_in, const int* in_sizes, int n_in,
                              void* d_out, int out_size) {
    const float* atoms = (const float*)d_in[0];
    const int*   preds = (const int*)  d_in[1];
    const float* Ws    = (const float*)d_in[2];
    const float* bs    = (const float*)d_in[3];
    const float* Wm    = (const float*)d_in[4];
    const float* bm    = (const float*)d_in[5];
    const float* attw  = (const float*)d_in[6];
    const float* dagw  = (const float*)d_in[7];
    const float* Wf    = (const float*)d_in[8];
    const float* bf    = (const float*)d_in[9];
    float* out = (float*)d_out;

    cudaFuncSetAttribute(k_dag, cudaFuncAttributeMaxDynamicSharedMemorySize, DSM_BYTES);

    k_zero<<<1, 1>>>();
    k_pre<<<(N_DAGS * NN) / 256, 128>>>(atoms, Wm, bm);
    k_dag<<<444, 128, DSM_BYTES>>>(atoms, preds, Wm, Ws, bs, attw, dagw);
    k_pool_partial<<<K2B, 128>>>();
    k_final<<<1, 512>>>(Wf, bf, out);
}